// round 7
// baseline (speedup 1.0000x reference)
#include <cuda_runtime.h>

typedef unsigned long long ull;
#define WST  128   // Ws row stride (all lanes read same d-row -> pad-free OK)
#define HPAD 132   // hq_s / hd_s row stride (conflict-free across rows)

// ---- f32x2 packed helpers ----
__device__ __forceinline__ ull pack2(float x, float y) {
    ull r; asm("mov.b64 %0, {%1,%2};" : "=l"(r) : "f"(x), "f"(y)); return r;
}
__device__ __forceinline__ void unpack2(ull v, float& x, float& y) {
    asm("mov.b64 {%0,%1}, %2;" : "=f"(x), "=f"(y) : "l"(v));
}
__device__ __forceinline__ ull fma2(ull a, ull b, ull c) {
    ull d; asm("fma.rn.f32x2 %0, %1, %2, %3;" : "=l"(d) : "l"(a), "l"(b), "l"(c)); return d;
}
__device__ __forceinline__ ull add2(ull a, ull b) {
    ull d; asm("add.rn.f32x2 %0, %1, %2;" : "=l"(d) : "l"(a), "l"(b)); return d;
}

// Mask dtype auto-detect: 0 = int32, 1 = uint8, 2 = float32
__device__ __forceinline__ bool mask_at(const void* p, int i, int mode) {
    if (mode == 0) return ((const int*)p)[i] != 0;
    if (mode == 2) return ((const float*)p)[i] != 0.0f;
    return ((const unsigned char*)p)[i] != 0;
}

// ============================================================================
// grid = 256 = (batch, n-half, m-half). 256 threads. 2 blocks/SM.
// Block owns a 32n x 32m output window. X rows read straight from global
// (compacted gather); W halves staged in smem one at a time.
// ============================================================================
__global__ void __launch_bounds__(256, 2)
fused_kernel(const float* __restrict__ query, const float* __restrict__ doc,
             const void* __restrict__ qmask, const void* __restrict__ dmask,
             const float* __restrict__ W1, const float* __restrict__ b1,
             const float* __restrict__ W2g, const float* __restrict__ b2g,
             float* __restrict__ out)
{
    extern __shared__ float sm[];
    float* Ws   = sm;                   // [128][WST]  W1 half (q then d)
    float* hq_s = Ws + 128 * WST;       // [32][HPAD]
    float* hd_s = hq_s + 32 * HPAD;     // [32][HPAD]
    float* w2_s = hd_s + 32 * HPAD;     // [3][128]
    float* b1s  = w2_s + 384;           // [128]
    int* nlist  = (int*)(b1s + 128);    // 34 (local n in window)
    int* mlist  = nlist + 34;           // 34 (local m in window)
    int* meta   = mlist + 34;           // [0]=notInt [1]=notF32 [2]=nvh [3]=mvh

    const int tid  = threadIdx.x;
    const int lane = tid & 31;
    const int wid  = tid >> 5;
    const int b    = blockIdx.x >> 2;
    const int nh   = (blockIdx.x >> 1) & 1;
    const int mh   = blockIdx.x & 1;

    if (tid < 4) meta[tid] = 0;
    __syncthreads();

    // ---- mask dtype detection + zero-fill own 32x32 output window
    {
        const unsigned* qw = (const unsigned*)qmask;
        int notInt = 0, notF32 = 0;
        for (int i = tid; i < 512; i += 256) {
            unsigned w = qw[i];
            notInt |= (w > 1u) ? 1 : 0;
            notF32 |= (w != 0u && w != 0x3F800000u) ? 1 : 0;
        }
        if (notInt) meta[0] = 1;
        if (notF32) meta[1] = 1;
    }
    float* obase = out + (size_t)((b * 64 + nh * 32) * 64 + mh * 32) * 3;
    {
        float4 z = make_float4(0.f, 0.f, 0.f, 0.f);
        for (int i = tid; i < 768; i += 256) {      // 32 rows x 24 float4
            int r = i / 24, c = i - r * 24;
            ((float4*)(obase + r * 192))[c] = z;
        }
    }
    __syncthreads();
    const int mode = (meta[0] == 0) ? 0 : ((meta[1] == 0) ? 2 : 1);

    // ---- per-warp roles: window ballots / W2 transpose / b1
    if (wid == 0) {
        bool v = mask_at(qmask, b * 64 + nh * 32 + lane, mode);
        unsigned mm = __ballot_sync(0xFFFFFFFFu, v);
        unsigned lt = (1u << lane) - 1u;
        if (v) nlist[__popc(mm & lt)] = lane;
        if (lane == 0) {
            int c = __popc(mm);
            meta[2] = c;
            if (c & 1) nlist[c] = 31 - __clz(mm);      // pad dup of last valid
        }
    } else if (wid == 1) {
        bool v = mask_at(dmask, b * 64 + mh * 32 + lane, mode);
        unsigned mm = __ballot_sync(0xFFFFFFFFu, v);
        unsigned lt = (1u << lane) - 1u;
        if (v) mlist[__popc(mm & lt)] = lane;
        if (lane == 0) {
            int c = __popc(mm);
            meta[3] = c;
            if (c & 1) mlist[c] = 31 - __clz(mm);
        }
    } else if (wid == 2 || wid == 3) {
        for (int i = tid - 64; i < 384; i += 64) {     // W2 (128,3) -> [o][h]
            int h = i / 3, o = i - h * 3;
            w2_s[o * 128 + h] = W2g[i];
        }
    } else if (wid == 4) {
        for (int i = lane; i < 128; i += 32) b1s[i] = b1[i];
    }

    // ---- stage W1 q-half (all threads)
    for (int i = tid; i < 4096; i += 256)
        *(float4*)(Ws + (i >> 5) * WST + (i & 31) * 4) = ((const float4*)W1)[i];
    __syncthreads();

    const int nvh = meta[2], mvh = meta[3];
    const int nvhp = (nvh + 1) & ~1;
    const int mvhp = (mvh + 1) & ~1;

    // thread h-mapping: 16 h-groups of 8, bank-rotated 4-float chunks
    const int hgrp = tid & 15;
    const int h0   = hgrp * 8;
    const int cj   = (hgrp >> 2) & 1;
    const int o0   = h0 + 4 * cj;
    const int o1   = h0 + 4 * (cj ^ 1);
    const int grp  = tid >> 4;

    // ---- hq: 2 rows x 8 h per thread, X gathered from global (LDG.128/4d)
    if (2 * grp < nvhp) {
        const int r0 = 2 * grp;
        const float4* x0 = (const float4*)(query +
                           (size_t)(b * 64 + nh * 32 + nlist[r0]) * 128);
        const float4* x1 = (const float4*)(query +
                           (size_t)(b * 64 + nh * 32 + nlist[r0 + 1]) * 128);
        ull a0=0,a1=0,a2=0,a3=0,a4=0,a5=0,a6=0,a7=0;
#pragma unroll 2
        for (int d4 = 0; d4 < 32; d4++) {
            float4 xa = x0[d4], xb = x1[d4];
            float va[4] = {xa.x, xa.y, xa.z, xa.w};
            float vb[4] = {xb.x, xb.y, xb.z, xb.w};
#pragma unroll
            for (int k = 0; k < 4; k++) {
                const float* wr = Ws + (4 * d4 + k) * WST;
                ulonglong2 wA = *(const ulonglong2*)(wr + o0);
                ulonglong2 wB = *(const ulonglong2*)(wr + o1);
                ull pa = pack2(va[k], va[k]), pb = pack2(vb[k], vb[k]);
                a0 = fma2(pa, wA.x, a0); a1 = fma2(pa, wA.y, a1);
                a2 = fma2(pa, wB.x, a2); a3 = fma2(pa, wB.y, a3);
                a4 = fma2(pb, wA.x, a4); a5 = fma2(pb, wA.y, a5);
                a6 = fma2(pb, wB.x, a6); a7 = fma2(pb, wB.y, a7);
            }
        }
        float v[8];
        float4 s;
        unpack2(a0, v[0], v[1]); unpack2(a1, v[2], v[3]);
        s = make_float4(v[0]+b1s[o0], v[1]+b1s[o0+1], v[2]+b1s[o0+2], v[3]+b1s[o0+3]);
        *(float4*)(hq_s + r0 * HPAD + o0) = s;
        unpack2(a2, v[4], v[5]); unpack2(a3, v[6], v[7]);
        s = make_float4(v[4]+b1s[o1], v[5]+b1s[o1+1], v[6]+b1s[o1+2], v[7]+b1s[o1+3]);
        *(float4*)(hq_s + r0 * HPAD + o1) = s;
        unpack2(a4, v[0], v[1]); unpack2(a5, v[2], v[3]);
        s = make_float4(v[0]+b1s[o0], v[1]+b1s[o0+1], v[2]+b1s[o0+2], v[3]+b1s[o0+3]);
        *(float4*)(hq_s + (r0+1) * HPAD + o0) = s;
        unpack2(a6, v[4], v[5]); unpack2(a7, v[6], v[7]);
        s = make_float4(v[4]+b1s[o1], v[5]+b1s[o1+1], v[6]+b1s[o1+2], v[7]+b1s[o1+3]);
        *(float4*)(hq_s + (r0+1) * HPAD + o1) = s;
    }
    __syncthreads();

    // ---- restage W1 d-half
    for (int i = tid; i < 4096; i += 256)
        *(float4*)(Ws + (i >> 5) * WST + (i & 31) * 4) =
            ((const float4*)(W1 + 16384))[i];
    __syncthreads();

    // ---- hd: 2 rows x 8 h per thread (no bias)
    if (2 * grp < mvhp) {
        const int r0 = 2 * grp;
        const float4* x0 = (const float4*)(doc +
                           (size_t)(b * 64 + mh * 32 + mlist[r0]) * 128);
        const float4* x1 = (const float4*)(doc +
                           (size_t)(b * 64 + mh * 32 + mlist[r0 + 1]) * 128);
        ull a0=0,a1=0,a2=0,a3=0,a4=0,a5=0,a6=0,a7=0;
#pragma unroll 2
        for (int d4 = 0; d4 < 32; d4++) {
            float4 xa = x0[d4], xb = x1[d4];
            float va[4] = {xa.x, xa.y, xa.z, xa.w};
            float vb[4] = {xb.x, xb.y, xb.z, xb.w};
#pragma unroll
            for (int k = 0; k < 4; k++) {
                const float* wr = Ws + (4 * d4 + k) * WST;
                ulonglong2 wA = *(const ulonglong2*)(wr + o0);
                ulonglong2 wB = *(const ulonglong2*)(wr + o1);
                ull pa = pack2(va[k], va[k]), pb = pack2(vb[k], vb[k]);
                a0 = fma2(pa, wA.x, a0); a1 = fma2(pa, wA.y, a1);
                a2 = fma2(pa, wB.x, a2); a3 = fma2(pa, wB.y, a3);
                a4 = fma2(pb, wA.x, a4); a5 = fma2(pb, wA.y, a5);
                a6 = fma2(pb, wB.x, a6); a7 = fma2(pb, wB.y, a7);
            }
        }
        float v[8];
        unpack2(a0, v[0], v[1]); unpack2(a1, v[2], v[3]);
        *(float4*)(hd_s + r0 * HPAD + o0) = make_float4(v[0], v[1], v[2], v[3]);
        unpack2(a2, v[4], v[5]); unpack2(a3, v[6], v[7]);
        *(float4*)(hd_s + r0 * HPAD + o1) = make_float4(v[4], v[5], v[6], v[7]);
        unpack2(a4, v[0], v[1]); unpack2(a5, v[2], v[3]);
        *(float4*)(hd_s + (r0+1) * HPAD + o0) = make_float4(v[0], v[1], v[2], v[3]);
        unpack2(a6, v[4], v[5]); unpack2(a7, v[6], v[7]);
        *(float4*)(hd_s + (r0+1) * HPAD + o1) = make_float4(v[4], v[5], v[6], v[7]);
    }
    __syncthreads();

    // ---- pairwise: <=256 tiles, 1 per thread, rows paired (i, i+count/2)
    const int nt = nvhp >> 1, mt = mvhp >> 1;
    const int total = nt * mt;
    if (tid < total) {
        const int ni = tid / mt;
        const int mi = tid - ni * mt;
        const float* pa0 = hq_s + ni * HPAD;
        const float* pa1 = hq_s + (ni + nt) * HPAD;
        const float* pd0 = hd_s + mi * HPAD;
        const float* pd1 = hd_s + (mi + mt) * HPAD;
        const float b2_0 = b2g[0], b2_1 = b2g[1], b2_2 = b2g[2];

        ull acc[4][3];
#pragma unroll
        for (int c = 0; c < 4; c++)
#pragma unroll
            for (int o = 0; o < 3; o++) acc[c][o] = 0ull;

#define COMBO(c, Alo, Ahi, Dlo, Dhi) do {                                   \
            ull tlo = add2((Alo), (Dlo));                                    \
            ull thi = add2((Ahi), (Dhi));                                    \
            float f0, f1, f2, f3;                                            \
            unpack2(tlo, f0, f1); unpack2(thi, f2, f3);                      \
            f0 = fmaxf(f0, 0.f); f1 = fmaxf(f1, 0.f);                        \
            f2 = fmaxf(f2, 0.f); f3 = fmaxf(f3, 0.f);                        \
            tlo = pack2(f0, f1); thi = pack2(f2, f3);                        \
            acc[c][0] = fma2(tlo, w0.x, acc[c][0]);                          \
            acc[c][0] = fma2(thi, w0.y, acc[c][0]);                          \
            acc[c][1] = fma2(tlo, w1.x, acc[c][1]);                          \
            acc[c][1] = fma2(thi, w1.y, acc[c][1]);                          \
            acc[c][2] = fma2(tlo, w2v.x, acc[c][2]);                         \
            acc[c][2] = fma2(thi, w2v.y, acc[c][2]);                         \
        } while (0)

#pragma unroll 4
        for (int h = 0; h < 128; h += 4) {
            ulonglong2 A0 = *(const ulonglong2*)(pa0 + h);
            ulonglong2 A1 = *(const ulonglong2*)(pa1 + h);
            ulonglong2 D0 = *(const ulonglong2*)(pd0 + h);
            ulonglong2 D1 = *(const ulonglong2*)(pd1 + h);
            ulonglong2 w0  = *(const ulonglong2*)(w2_s + h);
            ulonglong2 w1  = *(const ulonglong2*)(w2_s + 128 + h);
            ulonglong2 w2v = *(const ulonglong2*)(w2_s + 256 + h);
            COMBO(0, A0.x, A0.y, D0.x, D0.y);
            COMBO(1, A0.x, A0.y, D1.x, D1.y);
            COMBO(2, A1.x, A1.y, D0.x, D0.y);
            COMBO(3, A1.x, A1.y, D1.x, D1.y);
        }
#undef COMBO

        const int gn0 = nlist[ni], gn1 = nlist[ni + nt];
        const int gm0 = mlist[mi], gm1 = mlist[mi + mt];

#define WRITE(c, gn, gm) do {                                               \
            float lo, hi, s0, s1, s2;                                        \
            unpack2(acc[c][0], lo, hi); s0 = lo + hi + b2_0;                 \
            unpack2(acc[c][1], lo, hi); s1 = lo + hi + b2_1;                 \
            unpack2(acc[c][2], lo, hi); s2 = lo + hi + b2_2;                 \
            float* po = obase + (gn) * 192 + (gm) * 3;                       \
            po[0] = s0; po[1] = s1; po[2] = s2;                              \
        } while (0)

        WRITE(0, gn0, gm0);
        WRITE(1, gn0, gm1);
        WRITE(2, gn1, gm0);
        WRITE(3, gn1, gm1);
#undef WRITE
    }
}

// ============================================================================
extern "C" void kernel_launch(void* const* d_in, const int* in_sizes, int n_in,
                              void* d_out, int out_size)
{
    const float* query = (const float*)d_in[0];
    const float* doc   = (const float*)d_in[1];
    const void*  qmask = d_in[2];
    const void*  dmask = d_in[3];
    const float* W1    = (const float*)d_in[4];
    const float* b1    = (const float*)d_in[5];
    const float* W2    = (const float*)d_in[6];
    const float* b2    = (const float*)d_in[7];
    float* out = (float*)d_out;

    const int smem = (128 * WST + 32 * HPAD + 32 * HPAD + 384 + 128)
                         * (int)sizeof(float)
                     + (34 + 34 + 4) * (int)sizeof(int);   // ~99.5 KB

    cudaFuncSetAttribute(fused_kernel,
                         cudaFuncAttributeMaxDynamicSharedMemorySize, smem);

    fused_kernel<<<256, 256, smem>>>(query, doc, qmask, dmask, W1, b1, W2, b2, out);
}